// round 2
// baseline (speedup 1.0000x reference)
#include <cuda_runtime.h>
#include <math.h>

#define NN 100000
#define EE 1600000
#define DD 64
#define EDIM 16
#define SHC 9
#define FEAT 25   // SHC + EDIM

// ---------------- scratch (device globals; no runtime allocation) ----------
__device__ float  g_xt[(size_t)NN * DD];   // node MLP output
__device__ float  g_s [(size_t)NN * DD];   // segment sum -> agg (in place)
__device__ float  g_cnt[NN];               // per-node edge count
__device__ float  g_h [(size_t)NN * DD];   // out MLP result (pre-BN)
__device__ double g_sum[DD];               // BN stats
__device__ double g_sumsq[DD];

__device__ __forceinline__ float silu_f(float a) {
    return a / (1.0f + __expf(-a));
}

// ---------------- zero scratch --------------------------------------------
__global__ void zero_kernel() {
    int idx = blockIdx.x * blockDim.x + threadIdx.x;
    int stride = gridDim.x * blockDim.x;
    float4 z = make_float4(0.f, 0.f, 0.f, 0.f);
    for (int i = idx; i < NN * (DD / 4); i += stride)
        ((float4*)g_s)[i] = z;
    for (int i = idx; i < NN; i += stride)
        g_cnt[i] = 0.f;
    if (idx < DD) { g_sum[idx] = 0.0; g_sumsq[idx] = 0.0; }
}

// ---------------- node / output MLP (templated) ----------------------------
// IS_OUT=false: h = mlp(x row, 64->64->64)              -> g_xt
// IS_OUT=true : h = mlp(concat(agg,x) row, 128->64->64) -> g_h, + BN stats
template <bool IS_OUT>
__global__ __launch_bounds__(128)
void mlp_kernel(const float* __restrict__ x,
                const float* __restrict__ W1, const float* __restrict__ b1,
                const float* __restrict__ W2, const float* __restrict__ b2)
{
    constexpr int IND = IS_OUT ? 128 : 64;
    __shared__ float sW1[IND * DD];
    __shared__ float sW2[DD * DD];
    const int t = threadIdx.x;
    for (int i = t; i < IND * DD; i += 128) sW1[i] = W1[i];
    for (int i = t; i < DD * DD;  i += 128) sW2[i] = W2[i];
    __syncthreads();

    const int id = blockIdx.x * 128 + t;
    const bool valid = (id < NN);
    const int rid = valid ? id : (NN - 1);

    const float4* rowA;
    const float4* rowB = nullptr;
    if (IS_OUT) {
        rowA = (const float4*)(g_s + (size_t)rid * DD);     // agg (already divided)
        rowB = (const float4*)(x   + (size_t)rid * DD);
    } else {
        rowA = (const float4*)(x + (size_t)rid * DD);
    }

    float out[DD];
    {
        const float4* b2v = (const float4*)b2;
        #pragma unroll
        for (int q = 0; q < 16; q++) {
            float4 bv = b2v[q];
            out[4*q] = bv.x; out[4*q+1] = bv.y; out[4*q+2] = bv.z; out[4*q+3] = bv.w;
        }
    }

    #pragma unroll 1
    for (int ch = 0; ch < 4; ch++) {
        const int base = ch * 16;
        float h16[16];
        {
            const float4* b1v = (const float4*)(b1 + base);
            #pragma unroll
            for (int q = 0; q < 4; q++) {
                float4 bv = b1v[q];
                h16[4*q] = bv.x; h16[4*q+1] = bv.y; h16[4*q+2] = bv.z; h16[4*q+3] = bv.w;
            }
        }
        #pragma unroll 2
        for (int g = 0; g < IND / 4; g++) {
            float4 v;
            if (IS_OUT) v = (g < 16) ? rowA[g] : rowB[g - 16];
            else        v = rowA[g];
            const float fv[4] = {v.x, v.y, v.z, v.w};
            #pragma unroll
            for (int u = 0; u < 4; u++) {
                const float fm = fv[u];
                const float4* wr = (const float4*)(sW1 + (g*4 + u) * DD + base);
                #pragma unroll
                for (int q = 0; q < 4; q++) {
                    float4 w = wr[q];
                    h16[4*q]   += fm * w.x; h16[4*q+1] += fm * w.y;
                    h16[4*q+2] += fm * w.z; h16[4*q+3] += fm * w.w;
                }
            }
        }
        #pragma unroll
        for (int kk = 0; kk < 16; kk++) h16[kk] = silu_f(h16[kk]);
        #pragma unroll
        for (int kk = 0; kk < 16; kk++) {
            const float hv = h16[kk];
            const float4* wr = (const float4*)(sW2 + (base + kk) * DD);
            #pragma unroll
            for (int q = 0; q < 16; q++) {
                float4 w = wr[q];
                out[4*q]   += hv * w.x; out[4*q+1] += hv * w.y;
                out[4*q+2] += hv * w.z; out[4*q+3] += hv * w.w;
            }
        }
    }

    float* dst = IS_OUT ? g_h : g_xt;
    if (valid) {
        float4* o = (float4*)(dst + (size_t)id * DD);
        #pragma unroll
        for (int q = 0; q < 16; q++)
            o[q] = make_float4(out[4*q], out[4*q+1], out[4*q+2], out[4*q+3]);
    }

    if (IS_OUT) {
        // warp-reduced BN statistics, double accumulation in global
        #pragma unroll
        for (int j = 0; j < DD; j++) {
            float v = valid ? out[j] : 0.f;
            float s = v, sq = v * v;
            #pragma unroll
            for (int o = 16; o; o >>= 1) {
                s  += __shfl_down_sync(0xffffffffu, s,  o);
                sq += __shfl_down_sync(0xffffffffu, sq, o);
            }
            if ((t & 31) == 0) {
                atomicAdd(&g_sum[j],   (double)s);
                atomicAdd(&g_sumsq[j], (double)sq);
            }
        }
    }
}

// ---------------- fused edge kernel ----------------------------------------
// Per edge: SH(d) -> concat(edge_attr) -> MLP(25->64->64) -> * x_t[row]
//           -> atomicAdd into s[col]; count into cnt[col].
__global__ __launch_bounds__(128)
void edge_kernel(const float* __restrict__ pos,
                 const float* __restrict__ edge_attr,
                 const int*   __restrict__ row,
                 const int*   __restrict__ col,
                 const float* __restrict__ W1, const float* __restrict__ b1,
                 const float* __restrict__ W2, const float* __restrict__ b2)
{
    __shared__ float sW1[FEAT * DD];   // 6.25 KB
    __shared__ float sW2[DD * DD];     // 16 KB
    const int t = threadIdx.x;
    for (int i = t; i < FEAT * DD; i += 128) sW1[i] = W1[i];
    for (int i = t; i < DD * DD;   i += 128) sW2[i] = W2[i];
    __syncthreads();

    const int e = blockIdx.x * 128 + t;
    if (e >= EE) return;

    const int r = row[e];
    const int c = col[e];

    float px = pos[3*r]   - pos[3*c];
    float py = pos[3*r+1] - pos[3*c+1];
    float pz = pos[3*r+2] - pos[3*c+2];
    float len = sqrtf(px*px + py*py + pz*pz + 1e-12f);
    float dx = px / len, dy = py / len, dz = pz / len;
    float n2 = sqrtf(dx*dx + dy*dy + dz*dz) + 1e-10f;
    dx /= n2; dy /= n2; dz /= n2;

    float feat[FEAT];
    feat[0] = 0.28209479177387814f;
    feat[1] = 0.4886025119029199f * dy;
    feat[2] = 0.4886025119029199f * dz;
    feat[3] = 0.4886025119029199f * dx;
    feat[4] = 1.0925484305920792f * dx * dy;
    feat[5] = 1.0925484305920792f * dy * dz;
    feat[6] = 0.31539156525252005f * (3.0f * dz * dz - 1.0f);
    feat[7] = 1.0925484305920792f * dx * dz;
    feat[8] = 0.5462742152960396f * (dx*dx - dy*dy);
    {
        const float4* ea = (const float4*)(edge_attr + (size_t)e * EDIM);
        #pragma unroll
        for (int i = 0; i < 4; i++) {
            float4 v = ea[i];
            feat[SHC + 4*i]   = v.x; feat[SHC + 4*i+1] = v.y;
            feat[SHC + 4*i+2] = v.z; feat[SHC + 4*i+3] = v.w;
        }
    }

    float ew[DD];
    {
        const float4* b2v = (const float4*)b2;
        #pragma unroll
        for (int q = 0; q < 16; q++) {
            float4 bv = b2v[q];
            ew[4*q] = bv.x; ew[4*q+1] = bv.y; ew[4*q+2] = bv.z; ew[4*q+3] = bv.w;
        }
    }

    #pragma unroll 1
    for (int ch = 0; ch < 4; ch++) {
        const int base = ch * 16;
        float h16[16];
        {
            const float4* b1v = (const float4*)(b1 + base);
            #pragma unroll
            for (int q = 0; q < 4; q++) {
                float4 bv = b1v[q];
                h16[4*q] = bv.x; h16[4*q+1] = bv.y; h16[4*q+2] = bv.z; h16[4*q+3] = bv.w;
            }
        }
        #pragma unroll
        for (int m = 0; m < FEAT; m++) {
            const float fm = feat[m];
            const float4* wr = (const float4*)(sW1 + m * DD + base);
            #pragma unroll
            for (int q = 0; q < 4; q++) {
                float4 w = wr[q];
                h16[4*q]   += fm * w.x; h16[4*q+1] += fm * w.y;
                h16[4*q+2] += fm * w.z; h16[4*q+3] += fm * w.w;
            }
        }
        #pragma unroll
        for (int kk = 0; kk < 16; kk++) h16[kk] = silu_f(h16[kk]);
        #pragma unroll
        for (int kk = 0; kk < 16; kk++) {
            const float hv = h16[kk];
            const float4* wr = (const float4*)(sW2 + (base + kk) * DD);
            #pragma unroll
            for (int q = 0; q < 16; q++) {
                float4 w = wr[q];
                ew[4*q]   += hv * w.x; ew[4*q+1] += hv * w.y;
                ew[4*q+2] += hv * w.z; ew[4*q+3] += hv * w.w;
            }
        }
    }

    // msg = x_t[r] * ew ; scatter-add into s[c]
    const float4* xtr = (const float4*)(g_xt + (size_t)r * DD);
    float* sc = g_s + (size_t)c * DD;
    #pragma unroll
    for (int q = 0; q < 16; q++) {
        float4 xv = xtr[q];
        atomicAdd(sc + 4*q,     xv.x * ew[4*q]);
        atomicAdd(sc + 4*q + 1, xv.y * ew[4*q+1]);
        atomicAdd(sc + 4*q + 2, xv.z * ew[4*q+2]);
        atomicAdd(sc + 4*q + 3, xv.w * ew[4*q+3]);
    }
    atomicAdd(&g_cnt[c], 1.0f);
}

// ---------------- agg = s / max(cnt,1), in place ---------------------------
__global__ void agg_kernel() {
    int idx = blockIdx.x * 256 + threadIdx.x;
    if (idx >= NN * (DD / 4)) return;
    int node = idx >> 4;
    float inv = 1.0f / fmaxf(g_cnt[node], 1.0f);
    float4 v = ((float4*)g_s)[idx];
    v.x *= inv; v.y *= inv; v.z *= inv; v.w *= inv;
    ((float4*)g_s)[idx] = v;
}

// ---------------- batch-norm normalize -------------------------------------
__global__ void bn_kernel(float* __restrict__ outp,
                          const float* __restrict__ gamma,
                          const float* __restrict__ beta)
{
    int idx = blockIdx.x * 256 + threadIdx.x;
    if (idx >= NN * (DD / 4)) return;
    int jb = (idx & 15) * 4;
    float4 h = ((const float4*)g_h)[idx];
    float r[4] = {h.x, h.y, h.z, h.w};
    float rr[4];
    #pragma unroll
    for (int u = 0; u < 4; u++) {
        int j = jb + u;
        double mu  = g_sum[j]   * (1.0 / NN);
        double var = g_sumsq[j] * (1.0 / NN) - mu * mu;
        float  sc  = gamma[j] * rsqrtf(fmaxf((float)var, 0.f) + 1e-5f);
        rr[u] = (float)((double)r[u] - mu) * sc + beta[j];
    }
    ((float4*)outp)[idx] = make_float4(rr[0], rr[1], rr[2], rr[3]);
}

// ---------------- launch ----------------------------------------------------
extern "C" void kernel_launch(void* const* d_in, const int* in_sizes, int n_in,
                              void* d_out, int out_size)
{
    const float* x         = (const float*)d_in[0];
    const float* pos       = (const float*)d_in[1];
    const float* edge_attr = (const float*)d_in[2];
    const int*   row       = (const int*)  d_in[3];
    const int*   col       = (const int*)  d_in[4];
    const float* nW1 = (const float*)d_in[5];
    const float* nb1 = (const float*)d_in[6];
    const float* nW2 = (const float*)d_in[7];
    const float* nb2 = (const float*)d_in[8];
    const float* eW1 = (const float*)d_in[9];
    const float* eb1 = (const float*)d_in[10];
    const float* eW2 = (const float*)d_in[11];
    const float* eb2 = (const float*)d_in[12];
    const float* oW1 = (const float*)d_in[13];
    const float* ob1 = (const float*)d_in[14];
    const float* oW2 = (const float*)d_in[15];
    const float* ob2 = (const float*)d_in[16];
    const float* gam = (const float*)d_in[17];
    const float* bet = (const float*)d_in[18];
    float* outp = (float*)d_out;

    zero_kernel<<<512, 256>>>();
    mlp_kernel<false><<<(NN + 127) / 128, 128>>>(x, nW1, nb1, nW2, nb2);
    edge_kernel<<<EE / 128, 128>>>(pos, edge_attr, row, col, eW1, eb1, eW2, eb2);
    agg_kernel<<<(NN * (DD / 4) + 255) / 256, 256>>>();
    mlp_kernel<true><<<(NN + 127) / 128, 128>>>(x, oW1, ob1, oW2, ob2);
    bn_kernel<<<(NN * (DD / 4) + 255) / 256, 256>>>(outp, gam, bet);
}

// round 3
// speedup vs baseline: 1.2707x; 1.2707x over previous
#include <cuda_runtime.h>
#include <math.h>

#define NN 100000
#define EE 1600000
#define DD 64
#define EDIM 16
#define SHC 9
#define FEAT 25   // SHC + EDIM

typedef unsigned long long u64;

// ---------------- scratch (device globals; no runtime allocation) ----------
__device__ float  g_xt[(size_t)NN * DD];   // node MLP output
__device__ float  g_s [(size_t)NN * DD];   // segment sum -> agg (in place)
__device__ float  g_cnt[NN];               // per-node edge count
__device__ float  g_h [(size_t)NN * DD];   // out MLP result (pre-BN)
__device__ double g_sum[DD];               // BN stats
__device__ double g_sumsq[DD];

__device__ __forceinline__ float silu_f(float a) {
    return a / (1.0f + __expf(-a));
}

// ---------------- packed f32x2 helpers (Blackwell FFMA2 pipe) --------------
__device__ __forceinline__ u64 pk2(float x, float y) {
    u64 r; asm("mov.b64 %0, {%1,%2};" : "=l"(r) : "f"(x), "f"(y)); return r;
}
__device__ __forceinline__ void upk2(u64 v, float& x, float& y) {
    asm("mov.b64 {%0,%1}, %2;" : "=f"(x), "=f"(y) : "l"(v));
}
__device__ __forceinline__ void fma2(u64& d, u64 a, u64 b) {
    asm("fma.rn.f32x2 %0, %1, %2, %0;" : "+l"(d) : "l"(a), "l"(b));
}
__device__ __forceinline__ u64 mul2(u64 a, u64 b) {
    u64 r; asm("mul.rn.f32x2 %0, %1, %2;" : "=l"(r) : "l"(a), "l"(b)); return r;
}
// vector reduction: 4 floats per LSU lane instead of 1
__device__ __forceinline__ void red_add_v4(float* p, float a, float b, float c, float d) {
    asm volatile("red.global.add.v4.f32 [%0], {%1,%2,%3,%4};"
                 :: "l"(p), "f"(a), "f"(b), "f"(c), "f"(d) : "memory");
}

// ---------------- zero scratch --------------------------------------------
__global__ void zero_kernel() {
    int idx = blockIdx.x * blockDim.x + threadIdx.x;
    int stride = gridDim.x * blockDim.x;
    float4 z = make_float4(0.f, 0.f, 0.f, 0.f);
    for (int i = idx; i < NN * (DD / 4); i += stride)
        ((float4*)g_s)[i] = z;
    for (int i = idx; i < NN; i += stride)
        g_cnt[i] = 0.f;
    if (idx < DD) { g_sum[idx] = 0.0; g_sumsq[idx] = 0.0; }
}

// ---------------- node / output MLP (templated, f32x2 packed) ---------------
// IS_OUT=false: h = mlp(x row, 64->64->64)              -> g_xt
// IS_OUT=true : h = mlp(concat(agg,x) row, 128->64->64) -> g_h, + BN stats
template <bool IS_OUT>
__global__ __launch_bounds__(128)
void mlp_kernel(const float* __restrict__ x,
                const float* __restrict__ W1, const float* __restrict__ b1,
                const float* __restrict__ W2, const float* __restrict__ b2)
{
    constexpr int IND = IS_OUT ? 128 : 64;
    __shared__ __align__(16) float sW1[IND * DD];
    __shared__ __align__(16) float sW2[DD * DD];
    const int t = threadIdx.x;
    for (int i = t; i < IND * DD; i += 128) sW1[i] = W1[i];
    for (int i = t; i < DD * DD;  i += 128) sW2[i] = W2[i];
    __syncthreads();

    const int id = blockIdx.x * 128 + t;
    const bool valid = (id < NN);
    const int rid = valid ? id : (NN - 1);

    const float4* rowA;
    const float4* rowB = nullptr;
    if (IS_OUT) {
        rowA = (const float4*)(g_s + (size_t)rid * DD);     // agg (already divided)
        rowB = (const float4*)(x   + (size_t)rid * DD);
    } else {
        rowA = (const float4*)(x + (size_t)rid * DD);
    }

    u64 outp[32];   // 64 outputs, packed
    {
        const ulonglong2* b2v = (const ulonglong2*)b2;
        #pragma unroll
        for (int q = 0; q < 16; q++) { ulonglong2 bv = b2v[q]; outp[2*q] = bv.x; outp[2*q+1] = bv.y; }
    }

    #pragma unroll 1
    for (int ch = 0; ch < 4; ch++) {
        const int base = ch * 16;
        u64 hp[8];
        {
            const ulonglong2* b1v = (const ulonglong2*)(b1 + base);
            #pragma unroll
            for (int q = 0; q < 4; q++) { ulonglong2 bv = b1v[q]; hp[2*q] = bv.x; hp[2*q+1] = bv.y; }
        }
        #pragma unroll 2
        for (int g = 0; g < IND / 4; g++) {
            float4 v;
            if (IS_OUT) v = (g < 16) ? rowA[g] : rowB[g - 16];
            else        v = rowA[g];
            const float fv[4] = {v.x, v.y, v.z, v.w};
            #pragma unroll
            for (int u = 0; u < 4; u++) {
                const u64 fmp = pk2(fv[u], fv[u]);
                const ulonglong2* wr = (const ulonglong2*)(sW1 + (g*4 + u) * DD + base);
                #pragma unroll
                for (int q = 0; q < 4; q++) {
                    ulonglong2 w = wr[q];
                    fma2(hp[2*q], fmp, w.x);
                    fma2(hp[2*q+1], fmp, w.y);
                }
            }
        }
        float h16[16];
        #pragma unroll
        for (int i = 0; i < 8; i++) {
            float a, b; upk2(hp[i], a, b);
            h16[2*i] = silu_f(a); h16[2*i+1] = silu_f(b);
        }
        #pragma unroll
        for (int kk = 0; kk < 16; kk++) {
            const u64 hvp = pk2(h16[kk], h16[kk]);
            const ulonglong2* wr = (const ulonglong2*)(sW2 + (base + kk) * DD);
            #pragma unroll
            for (int q = 0; q < 16; q++) {
                ulonglong2 w = wr[q];
                fma2(outp[2*q], hvp, w.x);
                fma2(outp[2*q+1], hvp, w.y);
            }
        }
    }

    float* dst = IS_OUT ? g_h : g_xt;
    if (valid) {
        ulonglong2* o = (ulonglong2*)(dst + (size_t)id * DD);
        #pragma unroll
        for (int q = 0; q < 16; q++) {
            ulonglong2 w; w.x = outp[2*q]; w.y = outp[2*q+1];
            o[q] = w;
        }
    }

    if (IS_OUT) {
        // warp-reduced BN statistics, double accumulation in global
        #pragma unroll
        for (int jp = 0; jp < 32; jp++) {
            float va, vb; upk2(outp[jp], va, vb);
            if (!valid) { va = 0.f; vb = 0.f; }
            float s0 = va, q0 = va * va, s1 = vb, q1 = vb * vb;
            #pragma unroll
            for (int o = 16; o; o >>= 1) {
                s0 += __shfl_down_sync(0xffffffffu, s0, o);
                q0 += __shfl_down_sync(0xffffffffu, q0, o);
                s1 += __shfl_down_sync(0xffffffffu, s1, o);
                q1 += __shfl_down_sync(0xffffffffu, q1, o);
            }
            if ((t & 31) == 0) {
                atomicAdd(&g_sum[2*jp],     (double)s0);
                atomicAdd(&g_sumsq[2*jp],   (double)q0);
                atomicAdd(&g_sum[2*jp+1],   (double)s1);
                atomicAdd(&g_sumsq[2*jp+1], (double)q1);
            }
        }
    }
}

// ---------------- fused edge kernel (f32x2 packed + red.v4) -----------------
// Per edge: SH(d) -> concat(edge_attr) -> MLP(25->64->64) -> * x_t[row]
//           -> red.global.add.v4 into s[col]; count into cnt[col].
__global__ __launch_bounds__(128)
void edge_kernel(const float* __restrict__ pos,
                 const float* __restrict__ edge_attr,
                 const int*   __restrict__ row,
                 const int*   __restrict__ col,
                 const float* __restrict__ W1, const float* __restrict__ b1,
                 const float* __restrict__ W2, const float* __restrict__ b2)
{
    __shared__ __align__(16) float sW1[FEAT * DD];   // 6.25 KB
    __shared__ __align__(16) float sW2[DD * DD];     // 16 KB
    const int t = threadIdx.x;
    for (int i = t; i < FEAT * DD; i += 128) sW1[i] = W1[i];
    for (int i = t; i < DD * DD;   i += 128) sW2[i] = W2[i];
    __syncthreads();

    const int e = blockIdx.x * 128 + t;
    if (e >= EE) return;

    const int r = row[e];
    const int c = col[e];

    float px = pos[3*r]   - pos[3*c];
    float py = pos[3*r+1] - pos[3*c+1];
    float pz = pos[3*r+2] - pos[3*c+2];
    float len = sqrtf(px*px + py*py + pz*pz + 1e-12f);
    float dx = px / len, dy = py / len, dz = pz / len;
    float n2 = sqrtf(dx*dx + dy*dy + dz*dz) + 1e-10f;
    dx /= n2; dy /= n2; dz /= n2;

    float feat[FEAT];
    feat[0] = 0.28209479177387814f;
    feat[1] = 0.4886025119029199f * dy;
    feat[2] = 0.4886025119029199f * dz;
    feat[3] = 0.4886025119029199f * dx;
    feat[4] = 1.0925484305920792f * dx * dy;
    feat[5] = 1.0925484305920792f * dy * dz;
    feat[6] = 0.31539156525252005f * (3.0f * dz * dz - 1.0f);
    feat[7] = 1.0925484305920792f * dx * dz;
    feat[8] = 0.5462742152960396f * (dx*dx - dy*dy);
    {
        const float4* ea = (const float4*)(edge_attr + (size_t)e * EDIM);
        #pragma unroll
        for (int i = 0; i < 4; i++) {
            float4 v = ea[i];
            feat[SHC + 4*i]   = v.x; feat[SHC + 4*i+1] = v.y;
            feat[SHC + 4*i+2] = v.z; feat[SHC + 4*i+3] = v.w;
        }
    }

    u64 ewp[32];   // 64 outputs, packed f32x2
    {
        const ulonglong2* b2v = (const ulonglong2*)b2;
        #pragma unroll
        for (int q = 0; q < 16; q++) { ulonglong2 bv = b2v[q]; ewp[2*q] = bv.x; ewp[2*q+1] = bv.y; }
    }

    #pragma unroll 1
    for (int ch = 0; ch < 4; ch++) {
        const int base = ch * 16;
        u64 hp[8];
        {
            const ulonglong2* b1v = (const ulonglong2*)(b1 + base);
            #pragma unroll
            for (int q = 0; q < 4; q++) { ulonglong2 bv = b1v[q]; hp[2*q] = bv.x; hp[2*q+1] = bv.y; }
        }
        #pragma unroll
        for (int m = 0; m < FEAT; m++) {
            const u64 fmp = pk2(feat[m], feat[m]);
            const ulonglong2* wr = (const ulonglong2*)(sW1 + m * DD + base);
            #pragma unroll
            for (int q = 0; q < 4; q++) {
                ulonglong2 w = wr[q];
                fma2(hp[2*q], fmp, w.x);
                fma2(hp[2*q+1], fmp, w.y);
            }
        }
        float h16[16];
        #pragma unroll
        for (int i = 0; i < 8; i++) {
            float a, b; upk2(hp[i], a, b);
            h16[2*i] = silu_f(a); h16[2*i+1] = silu_f(b);
        }
        #pragma unroll
        for (int kk = 0; kk < 16; kk++) {
            const u64 hvp = pk2(h16[kk], h16[kk]);
            const ulonglong2* wr = (const ulonglong2*)(sW2 + (base + kk) * DD);
            #pragma unroll
            for (int q = 0; q < 16; q++) {
                ulonglong2 w = wr[q];
                fma2(ewp[2*q], hvp, w.x);
                fma2(ewp[2*q+1], hvp, w.y);
            }
        }
    }

    // msg = x_t[r] * ew ; vector scatter-add into s[c]
    const ulonglong2* xtr = (const ulonglong2*)(g_xt + (size_t)r * DD);
    float* sc = g_s + (size_t)c * DD;
    #pragma unroll
    for (int q = 0; q < 16; q++) {
        ulonglong2 xv = xtr[q];
        u64 m0 = mul2(xv.x, ewp[2*q]);
        u64 m1 = mul2(xv.y, ewp[2*q+1]);
        float f0, f1, f2, f3;
        upk2(m0, f0, f1);
        upk2(m1, f2, f3);
        red_add_v4(sc + 4*q, f0, f1, f2, f3);
    }
    atomicAdd(&g_cnt[c], 1.0f);
}

// ---------------- agg = s / max(cnt,1), in place ---------------------------
__global__ void agg_kernel() {
    int idx = blockIdx.x * 256 + threadIdx.x;
    if (idx >= NN * (DD / 4)) return;
    int node = idx >> 4;
    float inv = 1.0f / fmaxf(g_cnt[node], 1.0f);
    float4 v = ((float4*)g_s)[idx];
    v.x *= inv; v.y *= inv; v.z *= inv; v.w *= inv;
    ((float4*)g_s)[idx] = v;
}

// ---------------- batch-norm normalize -------------------------------------
__global__ void bn_kernel(float* __restrict__ outp,
                          const float* __restrict__ gamma,
                          const float* __restrict__ beta)
{
    int idx = blockIdx.x * 256 + threadIdx.x;
    if (idx >= NN * (DD / 4)) return;
    int jb = (idx & 15) * 4;
    float4 h = ((const float4*)g_h)[idx];
    float r[4] = {h.x, h.y, h.z, h.w};
    float rr[4];
    #pragma unroll
    for (int u = 0; u < 4; u++) {
        int j = jb + u;
        double mu  = g_sum[j]   * (1.0 / NN);
        double var = g_sumsq[j] * (1.0 / NN) - mu * mu;
        float  sc  = gamma[j] * rsqrtf(fmaxf((float)var, 0.f) + 1e-5f);
        rr[u] = (float)((double)r[u] - mu) * sc + beta[j];
    }
    ((float4*)outp)[idx] = make_float4(rr[0], rr[1], rr[2], rr[3]);
}

// ---------------- launch ----------------------------------------------------
extern "C" void kernel_launch(void* const* d_in, const int* in_sizes, int n_in,
                              void* d_out, int out_size)
{
    const float* x         = (const float*)d_in[0];
    const float* pos       = (const float*)d_in[1];
    const float* edge_attr = (const float*)d_in[2];
    const int*   row       = (const int*)  d_in[3];
    const int*   col       = (const int*)  d_in[4];
    const float* nW1 = (const float*)d_in[5];
    const float* nb1 = (const float*)d_in[6];
    const float* nW2 = (const float*)d_in[7];
    const float* nb2 = (const float*)d_in[8];
    const float* eW1 = (const float*)d_in[9];
    const float* eb1 = (const float*)d_in[10];
    const float* eW2 = (const float*)d_in[11];
    const float* eb2 = (const float*)d_in[12];
    const float* oW1 = (const float*)d_in[13];
    const float* ob1 = (const float*)d_in[14];
    const float* oW2 = (const float*)d_in[15];
    const float* ob2 = (const float*)d_in[16];
    const float* gam = (const float*)d_in[17];
    const float* bet = (const float*)d_in[18];
    float* outp = (float*)d_out;

    zero_kernel<<<512, 256>>>();
    mlp_kernel<false><<<(NN + 127) / 128, 128>>>(x, nW1, nb1, nW2, nb2);
    edge_kernel<<<EE / 128, 128>>>(pos, edge_attr, row, col, eW1, eb1, eW2, eb2);
    agg_kernel<<<(NN * (DD / 4) + 255) / 256, 256>>>();
    mlp_kernel<true><<<(NN + 127) / 128, 128>>>(x, oW1, ob1, oW2, ob2);
    bn_kernel<<<(NN * (DD / 4) + 255) / 256, 256>>>(outp, gam, bet);
}

// round 4
// speedup vs baseline: 1.4626x; 1.1510x over previous
#include <cuda_runtime.h>
#include <math.h>

#define NN 100000
#define EE 1600000
#define DD 64
#define EDIM 16
#define SHC 9
#define FEAT 25     // SHC + EDIM
#define TILE_E 128
#define NTILE (EE / TILE_E)   // 12500

typedef unsigned long long u64;

// ---------------- scratch (device globals; no runtime allocation) ----------
__device__ float  g_xt[(size_t)NN * DD];   // node MLP output
__device__ float  g_s [(size_t)NN * DD];   // segment sum -> agg (in place)
__device__ float  g_cnt[NN];               // per-node edge count
__device__ float  g_h [(size_t)NN * DD];   // out MLP result (pre-BN)
__device__ double g_sum[DD];               // BN stats
__device__ double g_sumsq[DD];

__device__ __forceinline__ float silu_f(float a) {
    return a / (1.0f + __expf(-a));
}

// ---------------- packed f32x2 helpers (Blackwell FFMA2 pipe) --------------
__device__ __forceinline__ u64 pk2(float x, float y) {
    u64 r; asm("mov.b64 %0, {%1,%2};" : "=l"(r) : "f"(x), "f"(y)); return r;
}
__device__ __forceinline__ void upk2(u64 v, float& x, float& y) {
    asm("mov.b64 {%0,%1}, %2;" : "=f"(x), "=f"(y) : "l"(v));
}
__device__ __forceinline__ void fma2(u64& d, u64 a, u64 b) {
    asm("fma.rn.f32x2 %0, %1, %2, %0;" : "+l"(d) : "l"(a), "l"(b));
}
__device__ __forceinline__ u64 mul2(u64 a, u64 b) {
    u64 r; asm("mul.rn.f32x2 %0, %1, %2;" : "=l"(r) : "l"(a), "l"(b)); return r;
}
__device__ __forceinline__ u64 silu2(u64 p) {
    float a, b; upk2(p, a, b);
    return pk2(silu_f(a), silu_f(b));
}
// vector reduction: 4 floats per LSU lane instead of 1
__device__ __forceinline__ void red_add_v4(float* p, float a, float b, float c, float d) {
    asm volatile("red.global.add.v4.f32 [%0], {%1,%2,%3,%4};"
                 :: "l"(p), "f"(a), "f"(b), "f"(c), "f"(d) : "memory");
}

// ---------------- zero scratch --------------------------------------------
__global__ void zero_kernel() {
    int idx = blockIdx.x * blockDim.x + threadIdx.x;
    int stride = gridDim.x * blockDim.x;
    float4 z = make_float4(0.f, 0.f, 0.f, 0.f);
    for (int i = idx; i < NN * (DD / 4); i += stride)
        ((float4*)g_s)[i] = z;
    for (int i = idx; i < NN; i += stride)
        g_cnt[i] = 0.f;
    if (idx < DD) { g_sum[idx] = 0.0; g_sumsq[idx] = 0.0; }
}

// ---------------- node / output MLP (unchanged from R3) ---------------------
template <bool IS_OUT>
__global__ __launch_bounds__(128)
void mlp_kernel(const float* __restrict__ x,
                const float* __restrict__ W1, const float* __restrict__ b1,
                const float* __restrict__ W2, const float* __restrict__ b2)
{
    constexpr int IND = IS_OUT ? 128 : 64;
    __shared__ __align__(16) float sW1[IND * DD];
    __shared__ __align__(16) float sW2[DD * DD];
    const int t = threadIdx.x;
    for (int i = t; i < IND * DD; i += 128) sW1[i] = W1[i];
    for (int i = t; i < DD * DD;  i += 128) sW2[i] = W2[i];
    __syncthreads();

    const int id = blockIdx.x * 128 + t;
    const bool valid = (id < NN);
    const int rid = valid ? id : (NN - 1);

    const float4* rowA;
    const float4* rowB = nullptr;
    if (IS_OUT) {
        rowA = (const float4*)(g_s + (size_t)rid * DD);
        rowB = (const float4*)(x   + (size_t)rid * DD);
    } else {
        rowA = (const float4*)(x + (size_t)rid * DD);
    }

    u64 outp[32];
    {
        const ulonglong2* b2v = (const ulonglong2*)b2;
        #pragma unroll
        for (int q = 0; q < 16; q++) { ulonglong2 bv = b2v[q]; outp[2*q] = bv.x; outp[2*q+1] = bv.y; }
    }

    #pragma unroll 1
    for (int ch = 0; ch < 4; ch++) {
        const int base = ch * 16;
        u64 hp[8];
        {
            const ulonglong2* b1v = (const ulonglong2*)(b1 + base);
            #pragma unroll
            for (int q = 0; q < 4; q++) { ulonglong2 bv = b1v[q]; hp[2*q] = bv.x; hp[2*q+1] = bv.y; }
        }
        #pragma unroll 2
        for (int g = 0; g < IND / 4; g++) {
            float4 v;
            if (IS_OUT) v = (g < 16) ? rowA[g] : rowB[g - 16];
            else        v = rowA[g];
            const float fv[4] = {v.x, v.y, v.z, v.w};
            #pragma unroll
            for (int u = 0; u < 4; u++) {
                const u64 fmp = pk2(fv[u], fv[u]);
                const ulonglong2* wr = (const ulonglong2*)(sW1 + (g*4 + u) * DD + base);
                #pragma unroll
                for (int q = 0; q < 4; q++) {
                    ulonglong2 w = wr[q];
                    fma2(hp[2*q], fmp, w.x);
                    fma2(hp[2*q+1], fmp, w.y);
                }
            }
        }
        float h16[16];
        #pragma unroll
        for (int i = 0; i < 8; i++) {
            float a, b; upk2(hp[i], a, b);
            h16[2*i] = silu_f(a); h16[2*i+1] = silu_f(b);
        }
        #pragma unroll
        for (int kk = 0; kk < 16; kk++) {
            const u64 hvp = pk2(h16[kk], h16[kk]);
            const ulonglong2* wr = (const ulonglong2*)(sW2 + (base + kk) * DD);
            #pragma unroll
            for (int q = 0; q < 16; q++) {
                ulonglong2 w = wr[q];
                fma2(outp[2*q], hvp, w.x);
                fma2(outp[2*q+1], hvp, w.y);
            }
        }
    }

    float* dst = IS_OUT ? g_h : g_xt;
    if (valid) {
        ulonglong2* o = (ulonglong2*)(dst + (size_t)id * DD);
        #pragma unroll
        for (int q = 0; q < 16; q++) {
            ulonglong2 w; w.x = outp[2*q]; w.y = outp[2*q+1];
            o[q] = w;
        }
    }

    if (IS_OUT) {
        #pragma unroll
        for (int jp = 0; jp < 32; jp++) {
            float va, vb; upk2(outp[jp], va, vb);
            if (!valid) { va = 0.f; vb = 0.f; }
            float s0 = va, q0 = va * va, s1 = vb, q1 = vb * vb;
            #pragma unroll
            for (int o = 16; o; o >>= 1) {
                s0 += __shfl_down_sync(0xffffffffu, s0, o);
                q0 += __shfl_down_sync(0xffffffffu, q0, o);
                s1 += __shfl_down_sync(0xffffffffu, s1, o);
                q1 += __shfl_down_sync(0xffffffffu, q1, o);
            }
            if ((t & 31) == 0) {
                atomicAdd(&g_sum[2*jp],     (double)s0);
                atomicAdd(&g_sumsq[2*jp],   (double)q0);
                atomicAdd(&g_sum[2*jp+1],   (double)s1);
                atomicAdd(&g_sumsq[2*jp+1], (double)q1);
            }
        }
    }
}

// ---------------- fused edge kernel: block-tiled register GEMM --------------
// Tile = 128 edges. Thread (er,nc) computes 8 edges x 8 outputs.
// smem: sW1[25*64] | sW2[64*64] | buf[64*128] (A1 rows 0..24 -> H -> EW)
__global__ __launch_bounds__(128)
void edge_kernel(const float* __restrict__ pos,
                 const float* __restrict__ edge_attr,
                 const int*   __restrict__ row,
                 const int*   __restrict__ col,
                 const float* __restrict__ W1, const float* __restrict__ b1,
                 const float* __restrict__ W2, const float* __restrict__ b2)
{
    extern __shared__ float smem[];
    float* sW1 = smem;                 // 1600 floats
    float* sW2 = smem + 1600;          // 4096 floats
    float* buf = smem + 5696;          // 64*128 = 8192 floats

    const int t  = threadIdx.x;
    const int er = t >> 3;     // 0..15 : edge sub-block (8 edges)
    const int nc = t & 7;      // 0..7  : output sub-block (8 outs)

    for (int i = t; i < FEAT * DD; i += 128) sW1[i] = W1[i];
    for (int i = t; i < DD * DD;   i += 128) sW2[i] = W2[i];
    float bb1[8], bb2[8];
    #pragma unroll
    for (int i = 0; i < 8; i++) { bb1[i] = b1[nc*8 + i]; bb2[i] = b2[nc*8 + i]; }
    __syncthreads();

    for (int tile = blockIdx.x; tile < NTILE; tile += gridDim.x) {
        const int e = tile * TILE_E + t;
        const int r = row[e];
        const int c = col[e];

        // ---- phase 1: per-edge features -> buf[k][t], k = 0..24 ----
        {
            float px = pos[3*r]   - pos[3*c];
            float py = pos[3*r+1] - pos[3*c+1];
            float pz = pos[3*r+2] - pos[3*c+2];
            float len = sqrtf(px*px + py*py + pz*pz + 1e-12f);
            float dx = px / len, dy = py / len, dz = pz / len;
            float n2 = sqrtf(dx*dx + dy*dy + dz*dz) + 1e-10f;
            dx /= n2; dy /= n2; dz /= n2;

            float feat[FEAT];
            feat[0] = 0.28209479177387814f;
            feat[1] = 0.4886025119029199f * dy;
            feat[2] = 0.4886025119029199f * dz;
            feat[3] = 0.4886025119029199f * dx;
            feat[4] = 1.0925484305920792f * dx * dy;
            feat[5] = 1.0925484305920792f * dy * dz;
            feat[6] = 0.31539156525252005f * (3.0f * dz * dz - 1.0f);
            feat[7] = 1.0925484305920792f * dx * dz;
            feat[8] = 0.5462742152960396f * (dx*dx - dy*dy);
            const float4* ea = (const float4*)(edge_attr + (size_t)e * EDIM);
            #pragma unroll
            for (int i = 0; i < 4; i++) {
                float4 v = ea[i];
                feat[SHC + 4*i]   = v.x; feat[SHC + 4*i+1] = v.y;
                feat[SHC + 4*i+2] = v.z; feat[SHC + 4*i+3] = v.w;
            }
            #pragma unroll
            for (int k = 0; k < FEAT; k++) buf[k*128 + t] = feat[k];
        }
        __syncthreads();

        // ---- phase 2: GEMM1  H[128x64] = A1[128x25] @ W1[25x64], K=25 ----
        u64 acc[4][8];
        #pragma unroll
        for (int n = 0; n < 8; n++) {
            u64 bp = pk2(bb1[n], bb1[n]);
            acc[0][n] = bp; acc[1][n] = bp; acc[2][n] = bp; acc[3][n] = bp;
        }
        #pragma unroll 5
        for (int k = 0; k < FEAT; k++) {
            const ulonglong2* ap = (const ulonglong2*)(buf + k*128 + er*8);
            ulonglong2 aA = ap[0], aB = ap[1];
            const float4* wp = (const float4*)(sW1 + k*64 + nc*8);
            float4 w0 = wp[0], w1 = wp[1];
            u64 bbp[8] = { pk2(w0.x,w0.x), pk2(w0.y,w0.y), pk2(w0.z,w0.z), pk2(w0.w,w0.w),
                           pk2(w1.x,w1.x), pk2(w1.y,w1.y), pk2(w1.z,w1.z), pk2(w1.w,w1.w) };
            #pragma unroll
            for (int n = 0; n < 8; n++) {
                fma2(acc[0][n], aA.x, bbp[n]);
                fma2(acc[1][n], aA.y, bbp[n]);
                fma2(acc[2][n], aB.x, bbp[n]);
                fma2(acc[3][n], aB.y, bbp[n]);
            }
        }
        __syncthreads();   // all A1 reads done before H overwrites buf

        // ---- silu + store H[k][e] (k = nc*8+n) ----
        #pragma unroll
        for (int n = 0; n < 8; n++) {
            int rowk = nc*8 + n;
            ulonglong2 s0, s1;
            s0.x = silu2(acc[0][n]); s0.y = silu2(acc[1][n]);
            s1.x = silu2(acc[2][n]); s1.y = silu2(acc[3][n]);
            ulonglong2* dp = (ulonglong2*)(buf + rowk*128 + er*8);
            dp[0] = s0; dp[1] = s1;
        }
        __syncthreads();

        // ---- phase 3: GEMM2  EW[128x64] = H[128x64] @ W2[64x64], K=64 ----
        #pragma unroll
        for (int n = 0; n < 8; n++) {
            u64 bp = pk2(bb2[n], bb2[n]);
            acc[0][n] = bp; acc[1][n] = bp; acc[2][n] = bp; acc[3][n] = bp;
        }
        #pragma unroll 4
        for (int k = 0; k < DD; k++) {
            const ulonglong2* ap = (const ulonglong2*)(buf + k*128 + er*8);
            ulonglong2 aA = ap[0], aB = ap[1];
            const float4* wp = (const float4*)(sW2 + k*64 + nc*8);
            float4 w0 = wp[0], w1 = wp[1];
            u64 bbp[8] = { pk2(w0.x,w0.x), pk2(w0.y,w0.y), pk2(w0.z,w0.z), pk2(w0.w,w0.w),
                           pk2(w1.x,w1.x), pk2(w1.y,w1.y), pk2(w1.z,w1.z), pk2(w1.w,w1.w) };
            #pragma unroll
            for (int n = 0; n < 8; n++) {
                fma2(acc[0][n], aA.x, bbp[n]);
                fma2(acc[1][n], aA.y, bbp[n]);
                fma2(acc[2][n], aB.x, bbp[n]);
                fma2(acc[3][n], aB.y, bbp[n]);
            }
        }
        __syncthreads();   // all H reads done before EW overwrites buf

        // ---- store EW[j][e] ----
        #pragma unroll
        for (int n = 0; n < 8; n++) {
            int rowk = nc*8 + n;
            ulonglong2 s0, s1;
            s0.x = acc[0][n]; s0.y = acc[1][n];
            s1.x = acc[2][n]; s1.y = acc[3][n];
            ulonglong2* dp = (ulonglong2*)(buf + rowk*128 + er*8);
            dp[0] = s0; dp[1] = s1;
        }
        __syncthreads();

        // ---- phase 4: msg = x_t[r] * ew ; scatter into s[c] ----
        {
            const float4* xtr = (const float4*)(g_xt + (size_t)r * DD);
            float* sc = g_s + (size_t)c * DD;
            #pragma unroll
            for (int q = 0; q < 16; q++) {
                float4 xv = xtr[q];
                float f0 = buf[(4*q+0)*128 + t] * xv.x;
                float f1 = buf[(4*q+1)*128 + t] * xv.y;
                float f2 = buf[(4*q+2)*128 + t] * xv.z;
                float f3 = buf[(4*q+3)*128 + t] * xv.w;
                red_add_v4(sc + 4*q, f0, f1, f2, f3);
            }
            atomicAdd(&g_cnt[c], 1.0f);
        }
        __syncthreads();   // buf reused by next tile's phase 1
    }
}

// ---------------- agg = s / max(cnt,1), in place ---------------------------
__global__ void agg_kernel() {
    int idx = blockIdx.x * 256 + threadIdx.x;
    if (idx >= NN * (DD / 4)) return;
    int node = idx >> 4;
    float inv = 1.0f / fmaxf(g_cnt[node], 1.0f);
    float4 v = ((float4*)g_s)[idx];
    v.x *= inv; v.y *= inv; v.z *= inv; v.w *= inv;
    ((float4*)g_s)[idx] = v;
}

// ---------------- batch-norm normalize -------------------------------------
__global__ void bn_kernel(float* __restrict__ outp,
                          const float* __restrict__ gamma,
                          const float* __restrict__ beta)
{
    int idx = blockIdx.x * 256 + threadIdx.x;
    if (idx >= NN * (DD / 4)) return;
    int jb = (idx & 15) * 4;
    float4 h = ((const float4*)g_h)[idx];
    float r[4] = {h.x, h.y, h.z, h.w};
    float rr[4];
    #pragma unroll
    for (int u = 0; u < 4; u++) {
        int j = jb + u;
        double mu  = g_sum[j]   * (1.0 / NN);
        double var = g_sumsq[j] * (1.0 / NN) - mu * mu;
        float  sc  = gamma[j] * rsqrtf(fmaxf((float)var, 0.f) + 1e-5f);
        rr[u] = (float)((double)r[u] - mu) * sc + beta[j];
    }
    ((float4*)outp)[idx] = make_float4(rr[0], rr[1], rr[2], rr[3]);
}

// ---------------- launch ----------------------------------------------------
#define EDGE_SMEM ((1600 + 4096 + 8192) * 4)   // 55552 bytes

extern "C" void kernel_launch(void* const* d_in, const int* in_sizes, int n_in,
                              void* d_out, int out_size)
{
    const float* x         = (const float*)d_in[0];
    const float* pos       = (const float*)d_in[1];
    const float* edge_attr = (const float*)d_in[2];
    const int*   row       = (const int*)  d_in[3];
    const int*   col       = (const int*)  d_in[4];
    const float* nW1 = (const float*)d_in[5];
    const float* nb1 = (const float*)d_in[6];
    const float* nW2 = (const float*)d_in[7];
    const float* nb2 = (const float*)d_in[8];
    const float* eW1 = (const float*)d_in[9];
    const float* eb1 = (const float*)d_in[10];
    const float* eW2 = (const float*)d_in[11];
    const float* eb2 = (const float*)d_in[12];
    const float* oW1 = (const float*)d_in[13];
    const float* ob1 = (const float*)d_in[14];
    const float* oW2 = (const float*)d_in[15];
    const float* ob2 = (const float*)d_in[16];
    const float* gam = (const float*)d_in[17];
    const float* bet = (const float*)d_in[18];
    float* outp = (float*)d_out;

    cudaFuncSetAttribute(edge_kernel,
                         cudaFuncAttributeMaxDynamicSharedMemorySize, EDGE_SMEM);

    zero_kernel<<<512, 256>>>();
    mlp_kernel<false><<<(NN + 127) / 128, 128>>>(x, nW1, nb1, nW2, nb2);
    edge_kernel<<<444, 128, EDGE_SMEM>>>(pos, edge_attr, row, col, eW1, eb1, eW2, eb2);
    agg_kernel<<<(NN * (DD / 4) + 255) / 256, 256>>>();
    mlp_kernel<true><<<(NN + 127) / 128, 128>>>(x, oW1, ob1, oW2, ob2);
    bn_kernel<<<(NN * (DD / 4) + 255) / 256, 256>>>(outp, gam, bet);
}

// round 5
// speedup vs baseline: 1.7884x; 1.2227x over previous
#include <cuda_runtime.h>
#include <math.h>

#define NN 100000
#define EE 1600000
#define DD 64
#define EDIM 16
#define SHC 9
#define FEAT 25     // SHC + EDIM
#define TILE_E 256
#define NTILE (EE / TILE_E)   // 6250

typedef unsigned long long u64;

// ---------------- scratch (device globals; no runtime allocation) ----------
__device__ float  g_xt[(size_t)NN * DD];   // node MLP output
__device__ float  g_s [(size_t)NN * DD];   // segment sum -> agg (in place)
__device__ float  g_cnt[NN];               // per-node edge count
__device__ float  g_h [(size_t)NN * DD];   // out MLP result (pre-BN)
__device__ double g_sum[DD];               // BN stats
__device__ double g_sumsq[DD];

__device__ __forceinline__ float silu_f(float a) {
    return a / (1.0f + __expf(-a));
}

// ---------------- packed f32x2 helpers --------------------------------------
__device__ __forceinline__ u64 pk2(float x, float y) {
    u64 r; asm("mov.b64 %0, {%1,%2};" : "=l"(r) : "f"(x), "f"(y)); return r;
}
__device__ __forceinline__ void upk2(u64 v, float& x, float& y) {
    asm("mov.b64 {%0,%1}, %2;" : "=f"(x), "=f"(y) : "l"(v));
}
__device__ __forceinline__ void fma2(u64& d, u64 a, u64 b) {
    asm("fma.rn.f32x2 %0, %1, %2, %0;" : "+l"(d) : "l"(a), "l"(b));
}
__device__ __forceinline__ u64 silu2(u64 p) {
    float a, b; upk2(p, a, b);
    return pk2(silu_f(a), silu_f(b));
}
// vector reduction: 4 floats per LSU lane instead of 1
__device__ __forceinline__ void red_add_v4(float* p, float a, float b, float c, float d) {
    asm volatile("red.global.add.v4.f32 [%0], {%1,%2,%3,%4};"
                 :: "l"(p), "f"(a), "f"(b), "f"(c), "f"(d) : "memory");
}

// ---------------- zero scratch --------------------------------------------
__global__ void zero_kernel() {
    int idx = blockIdx.x * blockDim.x + threadIdx.x;
    int stride = gridDim.x * blockDim.x;
    float4 z = make_float4(0.f, 0.f, 0.f, 0.f);
    for (int i = idx; i < NN * (DD / 4); i += stride)
        ((float4*)g_s)[i] = z;
    for (int i = idx; i < NN; i += stride)
        g_cnt[i] = 0.f;
    if (idx < DD) { g_sum[idx] = 0.0; g_sumsq[idx] = 0.0; }
}

// ---------------- node / output MLP (unchanged) -----------------------------
template <bool IS_OUT>
__global__ __launch_bounds__(128)
void mlp_kernel(const float* __restrict__ x,
                const float* __restrict__ W1, const float* __restrict__ b1,
                const float* __restrict__ W2, const float* __restrict__ b2)
{
    constexpr int IND = IS_OUT ? 128 : 64;
    __shared__ __align__(16) float sW1[IND * DD];
    __shared__ __align__(16) float sW2[DD * DD];
    const int t = threadIdx.x;
    for (int i = t; i < IND * DD; i += 128) sW1[i] = W1[i];
    for (int i = t; i < DD * DD;  i += 128) sW2[i] = W2[i];
    __syncthreads();

    const int id = blockIdx.x * 128 + t;
    const bool valid = (id < NN);
    const int rid = valid ? id : (NN - 1);

    const float4* rowA;
    const float4* rowB = nullptr;
    if (IS_OUT) {
        rowA = (const float4*)(g_s + (size_t)rid * DD);
        rowB = (const float4*)(x   + (size_t)rid * DD);
    } else {
        rowA = (const float4*)(x + (size_t)rid * DD);
    }

    u64 outp[32];
    {
        const ulonglong2* b2v = (const ulonglong2*)b2;
        #pragma unroll
        for (int q = 0; q < 16; q++) { ulonglong2 bv = b2v[q]; outp[2*q] = bv.x; outp[2*q+1] = bv.y; }
    }

    #pragma unroll 1
    for (int ch = 0; ch < 4; ch++) {
        const int base = ch * 16;
        u64 hp[8];
        {
            const ulonglong2* b1v = (const ulonglong2*)(b1 + base);
            #pragma unroll
            for (int q = 0; q < 4; q++) { ulonglong2 bv = b1v[q]; hp[2*q] = bv.x; hp[2*q+1] = bv.y; }
        }
        #pragma unroll 2
        for (int g = 0; g < IND / 4; g++) {
            float4 v;
            if (IS_OUT) v = (g < 16) ? rowA[g] : rowB[g - 16];
            else        v = rowA[g];
            const float fv[4] = {v.x, v.y, v.z, v.w};
            #pragma unroll
            for (int u = 0; u < 4; u++) {
                const u64 fmp = pk2(fv[u], fv[u]);
                const ulonglong2* wr = (const ulonglong2*)(sW1 + (g*4 + u) * DD + base);
                #pragma unroll
                for (int q = 0; q < 4; q++) {
                    ulonglong2 w = wr[q];
                    fma2(hp[2*q], fmp, w.x);
                    fma2(hp[2*q+1], fmp, w.y);
                }
            }
        }
        float h16[16];
        #pragma unroll
        for (int i = 0; i < 8; i++) {
            float a, b; upk2(hp[i], a, b);
            h16[2*i] = silu_f(a); h16[2*i+1] = silu_f(b);
        }
        #pragma unroll
        for (int kk = 0; kk < 16; kk++) {
            const u64 hvp = pk2(h16[kk], h16[kk]);
            const ulonglong2* wr = (const ulonglong2*)(sW2 + (base + kk) * DD);
            #pragma unroll
            for (int q = 0; q < 16; q++) {
                ulonglong2 w = wr[q];
                fma2(outp[2*q], hvp, w.x);
                fma2(outp[2*q+1], hvp, w.y);
            }
        }
    }

    float* dst = IS_OUT ? g_h : g_xt;
    if (valid) {
        ulonglong2* o = (ulonglong2*)(dst + (size_t)id * DD);
        #pragma unroll
        for (int q = 0; q < 16; q++) {
            ulonglong2 w; w.x = outp[2*q]; w.y = outp[2*q+1];
            o[q] = w;
        }
    }

    if (IS_OUT) {
        #pragma unroll
        for (int jp = 0; jp < 32; jp++) {
            float va, vb; upk2(outp[jp], va, vb);
            if (!valid) { va = 0.f; vb = 0.f; }
            float s0 = va, q0 = va * va, s1 = vb, q1 = vb * vb;
            #pragma unroll
            for (int o = 16; o; o >>= 1) {
                s0 += __shfl_down_sync(0xffffffffu, s0, o);
                q0 += __shfl_down_sync(0xffffffffu, q0, o);
                s1 += __shfl_down_sync(0xffffffffu, s1, o);
                q1 += __shfl_down_sync(0xffffffffu, q1, o);
            }
            if ((t & 31) == 0) {
                atomicAdd(&g_sum[2*jp],     (double)s0);
                atomicAdd(&g_sumsq[2*jp],   (double)q0);
                atomicAdd(&g_sum[2*jp+1],   (double)s1);
                atomicAdd(&g_sumsq[2*jp+1], (double)q1);
            }
        }
    }
}

// ---------------- fused edge kernel: 256-edge tile, register scatter --------
// Thread (er,nc): er = t>>3 in [0,32), nc = t&7. Computes 8 edges x 8 outputs.
// smem: sW1 | sW2 | sRow | sCol | buf (feat rows 0..24 overlaid by H rows 0..63)
__global__ __launch_bounds__(256, 2)
void edge_kernel(const float* __restrict__ pos,
                 const float* __restrict__ edge_attr,
                 const int*   __restrict__ row,
                 const int*   __restrict__ col,
                 const float* __restrict__ W1, const float* __restrict__ b1,
                 const float* __restrict__ W2, const float* __restrict__ b2)
{
    extern __shared__ float smem[];
    float* sW1  = smem;                      // 1600 floats
    float* sW2  = smem + 1600;               // 4096 floats
    int*   sRow = (int*)(smem + 5696);       // 256 ints
    int*   sCol = (int*)(smem + 5952);       // 256 ints
    float* buf  = smem + 6208;               // 64*256 = 16384 floats

    const int t  = threadIdx.x;
    const int er = t >> 3;     // 0..31 : edge sub-block (8 edges)
    const int nc = t & 7;      // 0..7  : output sub-block (8 outs)

    for (int i = t; i < FEAT * DD; i += 256) sW1[i] = W1[i];
    for (int i = t; i < DD * DD;   i += 256) sW2[i] = W2[i];
    float bb1[8], bb2[8];
    #pragma unroll
    for (int i = 0; i < 8; i++) { bb1[i] = b1[nc*8 + i]; bb2[i] = b2[nc*8 + i]; }
    __syncthreads();

    for (int tile = blockIdx.x; tile < NTILE; tile += gridDim.x) {
        const int e = tile * TILE_E + t;

        // ---- phase 1: per-edge features -> buf[k][t]; cache row/col ----
        {
            const int r = row[e];
            const int c = col[e];
            sRow[t] = r; sCol[t] = c;

            float px = pos[3*r]   - pos[3*c];
            float py = pos[3*r+1] - pos[3*c+1];
            float pz = pos[3*r+2] - pos[3*c+2];
            float len = sqrtf(px*px + py*py + pz*pz + 1e-12f);
            float dx = px / len, dy = py / len, dz = pz / len;
            float n2 = sqrtf(dx*dx + dy*dy + dz*dz) + 1e-10f;
            dx /= n2; dy /= n2; dz /= n2;

            float feat[FEAT];
            feat[0] = 0.28209479177387814f;
            feat[1] = 0.4886025119029199f * dy;
            feat[2] = 0.4886025119029199f * dz;
            feat[3] = 0.4886025119029199f * dx;
            feat[4] = 1.0925484305920792f * dx * dy;
            feat[5] = 1.0925484305920792f * dy * dz;
            feat[6] = 0.31539156525252005f * (3.0f * dz * dz - 1.0f);
            feat[7] = 1.0925484305920792f * dx * dz;
            feat[8] = 0.5462742152960396f * (dx*dx - dy*dy);
            const float4* ea = (const float4*)(edge_attr + (size_t)e * EDIM);
            #pragma unroll
            for (int i = 0; i < 4; i++) {
                float4 v = ea[i];
                feat[SHC + 4*i]   = v.x; feat[SHC + 4*i+1] = v.y;
                feat[SHC + 4*i+2] = v.z; feat[SHC + 4*i+3] = v.w;
            }
            #pragma unroll
            for (int k = 0; k < FEAT; k++) buf[k*TILE_E + t] = feat[k];
            atomicAdd(&g_cnt[c], 1.0f);
        }
        __syncthreads();

        // ---- phase 2: GEMM1  H = A1[256x25] @ W1[25x64] ----
        u64 acc[4][8];
        #pragma unroll
        for (int n = 0; n < 8; n++) {
            u64 bp = pk2(bb1[n], bb1[n]);
            acc[0][n] = bp; acc[1][n] = bp; acc[2][n] = bp; acc[3][n] = bp;
        }
        #pragma unroll 5
        for (int k = 0; k < FEAT; k++) {
            const ulonglong2* ap = (const ulonglong2*)(buf + k*TILE_E + er*8);
            ulonglong2 aA = ap[0], aB = ap[1];
            const float4* wp = (const float4*)(sW1 + k*64 + nc*8);
            float4 w0 = wp[0], w1 = wp[1];
            u64 bbp[8] = { pk2(w0.x,w0.x), pk2(w0.y,w0.y), pk2(w0.z,w0.z), pk2(w0.w,w0.w),
                           pk2(w1.x,w1.x), pk2(w1.y,w1.y), pk2(w1.z,w1.z), pk2(w1.w,w1.w) };
            #pragma unroll
            for (int n = 0; n < 8; n++) {
                fma2(acc[0][n], aA.x, bbp[n]);
                fma2(acc[1][n], aA.y, bbp[n]);
                fma2(acc[2][n], aB.x, bbp[n]);
                fma2(acc[3][n], aB.y, bbp[n]);
            }
        }
        __syncthreads();   // all feat reads done before H overlays buf

        // ---- silu + store H[k][e] (k = nc*8+n), overlaying feat region ----
        #pragma unroll
        for (int n = 0; n < 8; n++) {
            int rowk = nc*8 + n;
            ulonglong2 s0, s1;
            s0.x = silu2(acc[0][n]); s0.y = silu2(acc[1][n]);
            s1.x = silu2(acc[2][n]); s1.y = silu2(acc[3][n]);
            ulonglong2* dp = (ulonglong2*)(buf + rowk*TILE_E + er*8);
            dp[0] = s0; dp[1] = s1;
        }
        __syncthreads();

        // ---- phase 3: GEMM2  EW = H[256x64] @ W2[64x64] (stays in regs) ----
        #pragma unroll
        for (int n = 0; n < 8; n++) {
            u64 bp = pk2(bb2[n], bb2[n]);
            acc[0][n] = bp; acc[1][n] = bp; acc[2][n] = bp; acc[3][n] = bp;
        }
        #pragma unroll 4
        for (int k = 0; k < DD; k++) {
            const ulonglong2* ap = (const ulonglong2*)(buf + k*TILE_E + er*8);
            ulonglong2 aA = ap[0], aB = ap[1];
            const float4* wp = (const float4*)(sW2 + k*64 + nc*8);
            float4 w0 = wp[0], w1 = wp[1];
            u64 bbp[8] = { pk2(w0.x,w0.x), pk2(w0.y,w0.y), pk2(w0.z,w0.z), pk2(w0.w,w0.w),
                           pk2(w1.x,w1.x), pk2(w1.y,w1.y), pk2(w1.z,w1.z), pk2(w1.w,w1.w) };
            #pragma unroll
            for (int n = 0; n < 8; n++) {
                fma2(acc[0][n], aA.x, bbp[n]);
                fma2(acc[1][n], aA.y, bbp[n]);
                fma2(acc[2][n], aB.x, bbp[n]);
                fma2(acc[3][n], aB.y, bbp[n]);
            }
        }

        // ---- phase 4: scatter straight from registers ----
        // acc[i][n] holds edges (er*8+2i, er*8+2i+1) for output nc*8+n.
        #pragma unroll
        for (int i = 0; i < 4; i++) {
            float lo[8], hi[8];
            #pragma unroll
            for (int n = 0; n < 8; n++) upk2(acc[i][n], lo[n], hi[n]);
            const int e0 = er*8 + 2*i;
            const int r0 = sRow[e0],   c0 = sCol[e0];
            const int r1 = sRow[e0+1], c1 = sCol[e0+1];
            {
                const float4* xp = (const float4*)(g_xt + (size_t)r0 * DD + nc*8);
                float4 xa = xp[0], xb = xp[1];
                float* sc = g_s + (size_t)c0 * DD + nc*8;
                red_add_v4(sc,     lo[0]*xa.x, lo[1]*xa.y, lo[2]*xa.z, lo[3]*xa.w);
                red_add_v4(sc + 4, lo[4]*xb.x, lo[5]*xb.y, lo[6]*xb.z, lo[7]*xb.w);
            }
            {
                const float4* xp = (const float4*)(g_xt + (size_t)r1 * DD + nc*8);
                float4 xa = xp[0], xb = xp[1];
                float* sc = g_s + (size_t)c1 * DD + nc*8;
                red_add_v4(sc,     hi[0]*xa.x, hi[1]*xa.y, hi[2]*xa.z, hi[3]*xa.w);
                red_add_v4(sc + 4, hi[4]*xb.x, hi[5]*xb.y, hi[6]*xb.z, hi[7]*xb.w);
            }
        }
        __syncthreads();   // protect buf/sRow/sCol before next tile
    }
}

// ---------------- agg = s / max(cnt,1), in place ---------------------------
__global__ void agg_kernel() {
    int idx = blockIdx.x * 256 + threadIdx.x;
    if (idx >= NN * (DD / 4)) return;
    int node = idx >> 4;
    float inv = 1.0f / fmaxf(g_cnt[node], 1.0f);
    float4 v = ((float4*)g_s)[idx];
    v.x *= inv; v.y *= inv; v.z *= inv; v.w *= inv;
    ((float4*)g_s)[idx] = v;
}

// ---------------- batch-norm normalize -------------------------------------
__global__ void bn_kernel(float* __restrict__ outp,
                          const float* __restrict__ gamma,
                          const float* __restrict__ beta)
{
    int idx = blockIdx.x * 256 + threadIdx.x;
    if (idx >= NN * (DD / 4)) return;
    int jb = (idx & 15) * 4;
    float4 h = ((const float4*)g_h)[idx];
    float r[4] = {h.x, h.y, h.z, h.w};
    float rr[4];
    #pragma unroll
    for (int u = 0; u < 4; u++) {
        int j = jb + u;
        double mu  = g_sum[j]   * (1.0 / NN);
        double var = g_sumsq[j] * (1.0 / NN) - mu * mu;
        float  sc  = gamma[j] * rsqrtf(fmaxf((float)var, 0.f) + 1e-5f);
        rr[u] = (float)((double)r[u] - mu) * sc + beta[j];
    }
    ((float4*)outp)[idx] = make_float4(rr[0], rr[1], rr[2], rr[3]);
}

// ---------------- launch ----------------------------------------------------
#define EDGE_SMEM ((1600 + 4096 + 512 + 16384) * 4)   // 90368 bytes

extern "C" void kernel_launch(void* const* d_in, const int* in_sizes, int n_in,
                              void* d_out, int out_size)
{
    const float* x         = (const float*)d_in[0];
    const float* pos       = (const float*)d_in[1];
    const float* edge_attr = (const float*)d_in[2];
    const int*   row       = (const int*)  d_in[3];
    const int*   col       = (const int*)  d_in[4];
    const float* nW1 = (const float*)d_in[5];
    const float* nb1 = (const float*)d_in[6];
    const float* nW2 = (const float*)d_in[7];
    const float* nb2 = (const float*)d_in[8];
    const float* eW1 = (const float*)d_in[9];
    const float* eb1 = (const float*)d_in[10];
    const float* eW2 = (const float*)d_in[11];
    const float* eb2 = (const float*)d_in[12];
    const float* oW1 = (const float*)d_in[13];
    const float* ob1 = (const float*)d_in[14];
    const float* oW2 = (const float*)d_in[15];
    const float* ob2 = (const float*)d_in[16];
    const float* gam = (const float*)d_in[17];
    const float* bet = (const float*)d_in[18];
    float* outp = (float*)d_out;

    cudaFuncSetAttribute(edge_kernel,
                         cudaFuncAttributeMaxDynamicSharedMemorySize, EDGE_SMEM);

    zero_kernel<<<512, 256>>>();
    mlp_kernel<false><<<(NN + 127) / 128, 128>>>(x, nW1, nb1, nW2, nb2);
    edge_kernel<<<296, 256, EDGE_SMEM>>>(pos, edge_attr, row, col, eW1, eb1, eW2, eb2);
    agg_kernel<<<(NN * (DD / 4) + 255) / 256, 256>>>();
    mlp_kernel<true><<<(NN + 127) / 128, 128>>>(x, oW1, ob1, oW2, ob2);
    bn_kernel<<<(NN * (DD / 4) + 255) / 256, 256>>>(outp, gam, bet);
}